// round 7
// baseline (speedup 1.0000x reference)
#include <cuda_runtime.h>
#include <math.h>
#include <stdint.h>

#define BATCH 8192
#define IN_F  1024
#define OUT_F 2048
#define NTILES (OUT_F / 128)    // 16 col-tiles per row

// ---------------- device scratch (static; no allocations) ----------------
__device__ signed char   g_xh8[BATCH * IN_F];
__device__ signed char   g_xl8[BATCH * IN_F];
__device__ unsigned char g_wh8[OUT_F * IN_F];
__device__ unsigned char g_wl8[OUT_F * IN_F];
__device__ uint2        g_cand[BATCH * NTILES * 2];   // (valbits, colidx)
__device__ float        g_xx[OUT_F];
__device__ int          g_cnt1[OUT_F];
__device__ int          g_cnt2[OUT_F];
__device__ int          g_list1[OUT_F * BATCH];
__device__ int          g_list2[OUT_F * BATCH];
__device__ float        g_ds[OUT_F * IN_F];
__device__ unsigned int g_ncbits;

// ---------------- helpers ----------------
__device__ __forceinline__ uint32_t smem_u32(const void* p) {
    uint32_t a;
    asm("{ .reg .u64 t; cvta.to.shared.u64 t, %1; cvt.u32.u64 %0, t; }" : "=r"(a) : "l"(p));
    return a;
}
__device__ __forceinline__ void cp16(uint32_t dst, const void* src) {
    asm volatile("cp.async.cg.shared.global [%0], [%1], 16;\n" :: "r"(dst), "l"(src));
}
#define CP_COMMIT() asm volatile("cp.async.commit_group;\n" ::: "memory")
#define CP_WAIT2()  asm volatile("cp.async.wait_group 2;\n" ::: "memory")

__device__ __forceinline__ void ldsm4(uint32_t& r0, uint32_t& r1, uint32_t& r2, uint32_t& r3,
                                      uint32_t addr) {
    asm volatile("ldmatrix.sync.aligned.m8n8.x4.shared.b16 {%0,%1,%2,%3}, [%4];\n"
                 : "=r"(r0), "=r"(r1), "=r"(r2), "=r"(r3) : "r"(addr));
}
__device__ __forceinline__ void mma_s8u8(int* c, uint32_t a0, uint32_t a1, uint32_t a2,
                                         uint32_t a3, uint32_t b0, uint32_t b1) {
    asm volatile("mma.sync.aligned.m16n8k32.row.col.s32.s8.u8.s32 "
                 "{%0,%1,%2,%3}, {%4,%5,%6,%7}, {%8,%9}, {%0,%1,%2,%3};\n"
                 : "+r"(c[0]), "+r"(c[1]), "+r"(c[2]), "+r"(c[3])
                 : "r"(a0), "r"(a1), "r"(a2), "r"(a3), "r"(b0), "r"(b1));
}

// top-2 pair merge: incoming sorted pair (w1,j1,w2,j2) into (v1,c1,v2,c2).
// Tie-break: lower index wins (matches jax stable top_k).
__device__ __forceinline__ void merge2(float& v1, int& c1, float& v2, int& c2,
                                       float w1, int j1, float w2, int j2) {
    if (w1 > v1 || (w1 == v1 && j1 < c1)) {
        float t = v1; int tc = c1;
        if (w2 > t || (w2 == t && j2 < tc)) { t = w2; tc = j2; }
        v2 = t; c2 = tc; v1 = w1; c1 = j1;
    } else {
        if (w1 > v2 || (w1 == v2 && j1 < c2)) { v2 = w1; c2 = j1; }
    }
}
__device__ __forceinline__ void top2_add(float& v1, int& c1, float& v2, int& c2,
                                         float f, int idx) {
    if (f > v1)      { v2 = v1; c2 = c1; v1 = f; c1 = idx; }
    else if (f > v2) { v2 = f;  c2 = idx; }
}

// ---------------- K0: quantize fp32 -> int16 fixed point + zero accumulators ----------------
__global__ __launch_bounds__(256) void convert_kernel(const float* __restrict__ x,
                                                      const float* __restrict__ w) {
    const int NX4 = BATCH * IN_F / 4;
    const int NW4 = OUT_F * IN_F / 4;
    int t = blockIdx.x * blockDim.x + threadIdx.x;
    if (t < OUT_F) { g_xx[t] = 0.0f; g_cnt1[t] = 0; g_cnt2[t] = 0; }
    if (t == 0)    g_ncbits = 0u;
    if (t < NX4) {
        float4 v = ((const float4*)x)[t];
        uchar4 h, l;
        #pragma unroll
        for (int q = 0; q < 4; ++q) {
            float f = (&v.x)[q];
            int xq = __float2int_rn(f * 4096.0f);
            xq = max(min(xq, 32512), -32512);
            int hx = (xq + 128) >> 8;
            int lx = xq - (hx << 8);
            (&h.x)[q] = (unsigned char)(signed char)hx;
            (&l.x)[q] = (unsigned char)(signed char)lx;
        }
        ((uchar4*)g_xh8)[t] = h;
        ((uchar4*)g_xl8)[t] = l;
    } else if (t < NX4 + NW4) {
        int u = t - NX4;
        float4 v = ((const float4*)w)[u];
        uchar4 h, l;
        #pragma unroll
        for (int q = 0; q < 4; ++q) {
            float f = (&v.x)[q];
            int wq = __float2int_rn(f * 32768.0f);
            wq = max(min(wq, 32767), 0);
            (&h.x)[q] = (unsigned char)(wq >> 8);
            (&l.x)[q] = (unsigned char)(wq & 255);
        }
        ((uchar4*)g_wh8)[u] = h;
        ((uchar4*)g_wl8)[u] = l;
    }
}

// ---------------- K1: int8x3 GEMM + fused per-tile top-2 candidates ----------------
#define TILE_B  10240          // 128 rows * 80 B
#define OFF_XH  0
#define OFF_XL  10240
#define OFF_WH  20480
#define OFF_WL  30720
#define STAGE_B 40960
#define GEMM_SMEM (3 * STAGE_B)

__global__ __launch_bounds__(256, 1) void gemm_kernel(float* __restrict__ y) {
    extern __shared__ char smem[];
    const uint32_t sbase = smem_u32(smem);
    const int tid  = threadIdx.x;
    const int warp = tid >> 5;
    const int lane = tid & 31;
    const int mBase = blockIdx.y * 128;
    const int nBase = blockIdx.x * 128;

    #define LOAD_STAGE(sidx, kOff) do {                                           \
        uint32_t sb_ = sbase + (sidx) * STAGE_B;                                  \
        _Pragma("unroll")                                                         \
        for (int j_ = 0; j_ < 2; ++j_) {                                          \
            int c_   = tid + j_ * 256;                                            \
            int row_ = c_ >> 2;                                                   \
            int col_ = c_ & 3;                                                    \
            uint32_t dofs_ = (uint32_t)row_ * 80 + col_ * 16;                     \
            size_t gx_ = (size_t)(mBase + row_) * IN_F + (kOff) + col_ * 16;      \
            size_t gw_ = (size_t)(nBase + row_) * IN_F + (kOff) + col_ * 16;      \
            cp16(sb_ + OFF_XH + dofs_, g_xh8 + gx_);                              \
            cp16(sb_ + OFF_XL + dofs_, g_xl8 + gx_);                              \
            cp16(sb_ + OFF_WH + dofs_, g_wh8 + gw_);                              \
            cp16(sb_ + OFF_WL + dofs_, g_wl8 + gw_);                              \
        }                                                                         \
    } while (0)

    const int warp_m = warp >> 1;          // 0..3 -> 32 rows each
    const int warp_n = warp & 1;           // 0..1 -> 64 cols each
    const uint32_t aoff = (uint32_t)(warp_m * 32 + (lane & 15)) * 80 + ((lane >> 4) * 16);
    const uint32_t boff = (uint32_t)(warp_n * 64 + (lane & 7) + ((lane >> 4) << 3)) * 80
                        + (((lane >> 3) & 1) * 16);

    int hh[2][8][4], cc[2][8][4];
    #pragma unroll
    for (int i = 0; i < 2; ++i)
        #pragma unroll
        for (int j = 0; j < 8; ++j)
            #pragma unroll
            for (int q = 0; q < 4; ++q) { hh[i][j][q] = 0; cc[i][j][q] = 0; }

    LOAD_STAGE(0, 0);    CP_COMMIT();
    LOAD_STAGE(1, 64);   CP_COMMIT();
    LOAD_STAGE(2, 128);  CP_COMMIT();

    for (int kt = 0; kt < 16; ++kt) {
        CP_WAIT2();
        __syncthreads();
        const uint32_t sb = sbase + (kt % 3) * STAGE_B;

        #pragma unroll
        for (int ks = 0; ks < 2; ++ks) {
            uint32_t ah[2][4], al[2][4], bh[8][2], bl[8][2];
            #pragma unroll
            for (int i = 0; i < 2; ++i) {
                ldsm4(ah[i][0], ah[i][1], ah[i][2], ah[i][3],
                      sb + OFF_XH + aoff + i * 1280 + ks * 32);
                ldsm4(al[i][0], al[i][1], al[i][2], al[i][3],
                      sb + OFF_XL + aoff + i * 1280 + ks * 32);
            }
            #pragma unroll
            for (int j4 = 0; j4 < 4; ++j4) {
                uint32_t r0, r1, r2, r3;
                ldsm4(r0, r1, r2, r3, sb + OFF_WH + boff + j4 * 1280 + ks * 32);
                bh[j4 * 2][0] = r0; bh[j4 * 2][1] = r1;
                bh[j4 * 2 + 1][0] = r2; bh[j4 * 2 + 1][1] = r3;
                ldsm4(r0, r1, r2, r3, sb + OFF_WL + boff + j4 * 1280 + ks * 32);
                bl[j4 * 2][0] = r0; bl[j4 * 2][1] = r1;
                bl[j4 * 2 + 1][0] = r2; bl[j4 * 2 + 1][1] = r3;
            }
            #pragma unroll
            for (int i = 0; i < 2; ++i)
                #pragma unroll
                for (int j = 0; j < 8; ++j)
                    mma_s8u8(hh[i][j], ah[i][0], ah[i][1], ah[i][2], ah[i][3],
                             bh[j][0], bh[j][1]);
            #pragma unroll
            for (int i = 0; i < 2; ++i)
                #pragma unroll
                for (int j = 0; j < 8; ++j)
                    mma_s8u8(cc[i][j], ah[i][0], ah[i][1], ah[i][2], ah[i][3],
                             bl[j][0], bl[j][1]);
            #pragma unroll
            for (int i = 0; i < 2; ++i)
                #pragma unroll
                for (int j = 0; j < 8; ++j)
                    mma_s8u8(cc[i][j], al[i][0], al[i][1], al[i][2], al[i][3],
                             bh[j][0], bh[j][1]);
        }
        __syncthreads();
        if (kt + 3 < 16) LOAD_STAGE(kt % 3, (kt + 3) * 64);
        CP_COMMIT();
    }

    // ---- epilogue: y = hh*2^-11 + cc*2^-19; fused per-tile top-2 ----
    const float S_HH = 4.8828125e-4f;        // 2^-11
    const float S_CC = 1.9073486328125e-6f;  // 2^-19
    const int mrow = mBase + warp_m * 32 + (lane >> 2);
    const int ncol = nBase + warp_n * 64 + (lane & 3) * 2;

    __syncthreads();                          // pipeline done; reuse smem
    uint2* cs = (uint2*)smem;                 // [128 rows][2 warp_n][2 ranks]

    #pragma unroll
    for (int i = 0; i < 2; ++i) {
        float v1a = -INFINITY, v2a = -INFINITY; int c1a = 0x7fffffff, c2a = 0x7fffffff;
        float v1b = -INFINITY, v2b = -INFINITY; int c1b = 0x7fffffff, c2b = 0x7fffffff;
        #pragma unroll
        for (int j = 0; j < 8; ++j) {
            int m0 = mrow + i * 16;
            int n0 = ncol + j * 8;
            float v0 = fmaf((float)hh[i][j][0], S_HH, (float)cc[i][j][0] * S_CC);
            float v1 = fmaf((float)hh[i][j][1], S_HH, (float)cc[i][j][1] * S_CC);
            float v2 = fmaf((float)hh[i][j][2], S_HH, (float)cc[i][j][2] * S_CC);
            float v3 = fmaf((float)hh[i][j][3], S_HH, (float)cc[i][j][3] * S_CC);
            *(float2*)&y[(size_t)m0 * OUT_F + n0]       = make_float2(v0, v1);
            *(float2*)&y[(size_t)(m0 + 8) * OUT_F + n0] = make_float2(v2, v3);
            top2_add(v1a, c1a, v2a, c2a, v0, n0);
            top2_add(v1a, c1a, v2a, c2a, v1, n0 + 1);
            top2_add(v1b, c1b, v2b, c2b, v2, n0);
            top2_add(v1b, c1b, v2b, c2b, v3, n0 + 1);
        }
        // quad merge (lanes sharing a row differ only in lane&3)
        #pragma unroll
        for (int mk = 1; mk <= 2; mk <<= 1) {
            float w1 = __shfl_xor_sync(0xffffffffu, v1a, mk);
            int   j1 = __shfl_xor_sync(0xffffffffu, c1a, mk);
            float w2 = __shfl_xor_sync(0xffffffffu, v2a, mk);
            int   j2 = __shfl_xor_sync(0xffffffffu, c2a, mk);
            merge2(v1a, c1a, v2a, c2a, w1, j1, w2, j2);
            w1 = __shfl_xor_sync(0xffffffffu, v1b, mk);
            j1 = __shfl_xor_sync(0xffffffffu, c1b, mk);
            w2 = __shfl_xor_sync(0xffffffffu, v2b, mk);
            j2 = __shfl_xor_sync(0xffffffffu, c2b, mk);
            merge2(v1b, c1b, v2b, c2b, w1, j1, w2, j2);
        }
        if ((lane & 3) == 0) {
            int ra = warp_m * 32 + (lane >> 2) + i * 16;       // h=0 row
            int rb = ra + 8;                                    // h=1 row
            cs[(ra * 2 + warp_n) * 2 + 0] = make_uint2(__float_as_uint(v1a), (uint32_t)c1a);
            cs[(ra * 2 + warp_n) * 2 + 1] = make_uint2(__float_as_uint(v2a), (uint32_t)c2a);
            cs[(rb * 2 + warp_n) * 2 + 0] = make_uint2(__float_as_uint(v1b), (uint32_t)c1b);
            cs[(rb * 2 + warp_n) * 2 + 1] = make_uint2(__float_as_uint(v2b), (uint32_t)c2b);
        }
    }
    __syncthreads();
    if (tid < 128) {
        uint2 p0 = cs[(tid * 2 + 0) * 2 + 0], p1 = cs[(tid * 2 + 0) * 2 + 1];
        uint2 q0 = cs[(tid * 2 + 1) * 2 + 0], q1 = cs[(tid * 2 + 1) * 2 + 1];
        float v1 = __uint_as_float(p0.x), v2 = __uint_as_float(p1.x);
        int   c1 = (int)p0.y,             c2 = (int)p1.y;
        merge2(v1, c1, v2, c2, __uint_as_float(q0.x), (int)q0.y,
               __uint_as_float(q1.x), (int)q1.y);
        size_t o = ((size_t)(mBase + tid) * NTILES + blockIdx.x) * 2;
        g_cand[o + 0] = make_uint2(__float_as_uint(v1), (uint32_t)c1);
        g_cand[o + 1] = make_uint2(__float_as_uint(v2), (uint32_t)c2);
    }
    #undef LOAD_STAGE
}

// ---------------- K2: reduce 32 candidates/row -> top-2 + xx + lists ----------------
__global__ void topk_reduce_kernel() {
    int b    = (blockIdx.x * blockDim.x + threadIdx.x) >> 5;
    int lane = threadIdx.x & 31;
    if (b >= BATCH) return;
    uint2 c = g_cand[(size_t)b * 32 + lane];    // 16 tiles x 2 ranks = 32 = warp width
    float v1 = __uint_as_float(c.x);
    int   i1 = (int)c.y;
    float v2 = -INFINITY;
    int   i2 = 0x7fffffff;
    #pragma unroll
    for (int off = 16; off > 0; off >>= 1) {
        float w1 = __shfl_down_sync(0xffffffffu, v1, off);
        int   j1 = __shfl_down_sync(0xffffffffu, i1, off);
        float w2 = __shfl_down_sync(0xffffffffu, v2, off);
        int   j2 = __shfl_down_sync(0xffffffffu, i2, off);
        merge2(v1, i1, v2, i2, w1, j1, w2, j2);
    }
    if (lane == 0) {
        int s1 = atomicAdd(&g_cnt1[i1], 1);
        g_list1[i1 * BATCH + s1] = b;
        int s2 = atomicAdd(&g_cnt2[i2], 1);
        g_list2[i2 * BATCH + s2] = b;
        atomicAdd(&g_xx[i1], v1);
        atomicAdd(&g_xx[i2], -0.4f * v2);
    }
}

// ---------------- K3: fused ds = yl@x - xx*W  and  nc = max|ds| ----------------
__global__ __launch_bounds__(256) void ds_kernel(const float* __restrict__ x,
                                                 const float* __restrict__ W) {
    __shared__ float red[8];
    const int o = blockIdx.x;
    const int t = threadIdx.x;
    float4 wv = ((const float4*)W)[o * 256 + t];
    float s = -g_xx[o];
    float4 acc = make_float4(s * wv.x, s * wv.y, s * wv.z, s * wv.w);

    int n1 = g_cnt1[o];
    const int* l1 = g_list1 + (size_t)o * BATCH;
    for (int j = 0; j < n1; ++j) {
        int b = l1[j];
        float4 xv = ((const float4*)x)[b * 256 + t];
        acc.x += xv.x; acc.y += xv.y; acc.z += xv.z; acc.w += xv.w;
    }
    int n2 = g_cnt2[o];
    const int* l2 = g_list2 + (size_t)o * BATCH;
    for (int j = 0; j < n2; ++j) {
        int b = l2[j];
        float4 xv = ((const float4*)x)[b * 256 + t];
        acc.x -= 0.4f * xv.x; acc.y -= 0.4f * xv.y;
        acc.z -= 0.4f * xv.z; acc.w -= 0.4f * xv.w;
    }
    ((float4*)g_ds)[o * 256 + t] = acc;

    float m = fmaxf(fmaxf(fabsf(acc.x), fabsf(acc.y)), fmaxf(fabsf(acc.z), fabsf(acc.w)));
    #pragma unroll
    for (int off = 16; off > 0; off >>= 1)
        m = fmaxf(m, __shfl_down_sync(0xffffffffu, m, off));
    if ((t & 31) == 0) red[t >> 5] = m;
    __syncthreads();
    if (t < 8) {
        float v = red[t];
        #pragma unroll
        for (int off = 4; off > 0; off >>= 1)
            v = fmaxf(v, __shfl_down_sync(0xffu, v, off));
        if (t == 0) atomicMax(&g_ncbits, __float_as_uint(v));
    }
}

// ---------------- K4: new_W = W + 0.02 * ds / nc ----------------
__global__ void update_kernel(const float* __restrict__ W, float* __restrict__ outW) {
    float nc = fmaxf(__uint_as_float(g_ncbits), 1e-30f);
    float s  = 0.02f / nc;
    int t = blockIdx.x * blockDim.x + threadIdx.x;
    float4 w = ((const float4*)W)[t];
    float4 d = ((const float4*)g_ds)[t];
    ((float4*)outW)[t] = make_float4(fmaf(s, d.x, w.x), fmaf(s, d.y, w.y),
                                     fmaf(s, d.z, w.z), fmaf(s, d.w, w.w));
}

// ---------------- launch ----------------
extern "C" void kernel_launch(void* const* d_in, const int* in_sizes, int n_in,
                              void* d_out, int out_size) {
    const float* x = (const float*)d_in[0];   // [8192, 1024] f32
    const float* w = (const float*)d_in[1];   // [2048, 1024] f32
    float* y    = (float*)d_out;                              // [8192, 2048]
    float* outW = (float*)d_out + (size_t)BATCH * OUT_F;      // [2048, 1024]

    cudaFuncSetAttribute(gemm_kernel, cudaFuncAttributeMaxDynamicSharedMemorySize, GEMM_SMEM);

    const int NTOT4 = (BATCH * IN_F + OUT_F * IN_F) / 4;
    convert_kernel<<<(NTOT4 + 255) / 256, 256>>>(x, w);
    gemm_kernel<<<dim3(OUT_F / 128, BATCH / 128), 256, GEMM_SMEM>>>(y);
    topk_reduce_kernel<<<BATCH * 32 / 256, 256>>>();
    ds_kernel<<<OUT_F, 256>>>(x, w);
    update_kernel<<<(OUT_F * IN_F / 4) / 256, 256>>>(w, outW);
}

// round 8
// speedup vs baseline: 1.0661x; 1.0661x over previous
#include <cuda_runtime.h>
#include <math.h>
#include <stdint.h>

#define BATCH 8192
#define IN_F  1024
#define OUT_F 2048

// ---------------- device scratch (static; no allocations) ----------------
__device__ signed char   g_xh8[BATCH * IN_F];
__device__ signed char   g_xl8[BATCH * IN_F];
__device__ unsigned char g_wh8[OUT_F * IN_F];
__device__ unsigned char g_wl8[OUT_F * IN_F];
__device__ float        g_xx[OUT_F];
__device__ int          g_cnt1[OUT_F];
__device__ int          g_cnt2[OUT_F];
__device__ int          g_list1[OUT_F * BATCH];
__device__ int          g_list2[OUT_F * BATCH];
__device__ float        g_ds[OUT_F * IN_F];
__device__ unsigned int g_ncbits;

// ---------------- helpers ----------------
__device__ __forceinline__ uint32_t smem_u32(const void* p) {
    uint32_t a;
    asm("{ .reg .u64 t; cvta.to.shared.u64 t, %1; cvt.u32.u64 %0, t; }" : "=r"(a) : "l"(p));
    return a;
}
__device__ __forceinline__ void cp16(uint32_t dst, const void* src) {
    asm volatile("cp.async.cg.shared.global [%0], [%1], 16;\n" :: "r"(dst), "l"(src));
}
#define CP_COMMIT() asm volatile("cp.async.commit_group;\n" ::: "memory")
#define CP_WAIT2()  asm volatile("cp.async.wait_group 2;\n" ::: "memory")

__device__ __forceinline__ void ldsm4(uint32_t& r0, uint32_t& r1, uint32_t& r2, uint32_t& r3,
                                      uint32_t addr) {
    asm volatile("ldmatrix.sync.aligned.m8n8.x4.shared.b16 {%0,%1,%2,%3}, [%4];\n"
                 : "=r"(r0), "=r"(r1), "=r"(r2), "=r"(r3) : "r"(addr));
}
__device__ __forceinline__ void mma_s8u8(int* c, uint32_t a0, uint32_t a1, uint32_t a2,
                                         uint32_t a3, uint32_t b0, uint32_t b1) {
    asm volatile("mma.sync.aligned.m16n8k32.row.col.s32.s8.u8.s32 "
                 "{%0,%1,%2,%3}, {%4,%5,%6,%7}, {%8,%9}, {%0,%1,%2,%3};\n"
                 : "+r"(c[0]), "+r"(c[1]), "+r"(c[2]), "+r"(c[3])
                 : "r"(a0), "r"(a1), "r"(a2), "r"(a3), "r"(b0), "r"(b1));
}

// merge a sorted top-2 pair (w1,j1,w2,j2) into (v1,c1,v2,c2); ties -> lower index
__device__ __forceinline__ void merge2(float& v1, int& c1, float& v2, int& c2,
                                       float w1, int j1, float w2, int j2) {
    if (w1 > v1 || (w1 == v1 && j1 < c1)) {
        float t = v1; int tc = c1;
        if (w2 > t || (w2 == t && j2 < tc)) { t = w2; tc = j2; }
        v2 = t; c2 = tc; v1 = w1; c1 = j1;
    } else {
        if (w1 > v2 || (w1 == v2 && j1 < c2)) { v2 = w1; c2 = j1; }
    }
}
__device__ __forceinline__ void top2_add(float& v1, int& c1, float& v2, int& c2,
                                         float f, int idx) {
    if (f > v1)      { v2 = v1; c2 = c1; v1 = f; c1 = idx; }
    else if (f > v2) { v2 = f;  c2 = idx; }
}

// ---------------- K0: quantize fp32 -> int16 fixed point + zero accumulators ----------------
__global__ __launch_bounds__(256) void convert_kernel(const float* __restrict__ x,
                                                      const float* __restrict__ w) {
    const int NX4 = BATCH * IN_F / 4;
    const int NW4 = OUT_F * IN_F / 4;
    int t = blockIdx.x * blockDim.x + threadIdx.x;
    if (t < OUT_F) { g_xx[t] = 0.0f; g_cnt1[t] = 0; g_cnt2[t] = 0; }
    if (t == 0)    g_ncbits = 0u;
    if (t < NX4) {
        float4 v = ((const float4*)x)[t];
        uchar4 h, l;
        #pragma unroll
        for (int q = 0; q < 4; ++q) {
            float f = (&v.x)[q];
            int xq = __float2int_rn(f * 4096.0f);
            xq = max(min(xq, 32512), -32512);
            int hx = (xq + 128) >> 8;
            int lx = xq - (hx << 8);
            (&h.x)[q] = (unsigned char)(signed char)hx;
            (&l.x)[q] = (unsigned char)(signed char)lx;
        }
        ((uchar4*)g_xh8)[t] = h;
        ((uchar4*)g_xl8)[t] = l;
    } else if (t < NX4 + NW4) {
        int u = t - NX4;
        float4 v = ((const float4*)w)[u];
        uchar4 h, l;
        #pragma unroll
        for (int q = 0; q < 4; ++q) {
            float f = (&v.x)[q];
            int wq = __float2int_rn(f * 32768.0f);
            wq = max(min(wq, 32767), 0);
            (&h.x)[q] = (unsigned char)(wq >> 8);
            (&l.x)[q] = (unsigned char)(wq & 255);
        }
        ((uchar4*)g_wh8)[u] = h;
        ((uchar4*)g_wl8)[u] = l;
    }
}

// ---------------- K1: int8x3 GEMM via mma.sync  y = x @ W^T (round-6 proven) ----------------
#define TILE_B  10240          // 128 rows * 80 B
#define OFF_XH  0
#define OFF_XL  10240
#define OFF_WH  20480
#define OFF_WL  30720
#define STAGE_B 40960
#define GEMM_SMEM (3 * STAGE_B)

__global__ __launch_bounds__(256, 1) void gemm_kernel(float* __restrict__ y) {
    extern __shared__ char smem[];
    const uint32_t sbase = smem_u32(smem);
    const int tid  = threadIdx.x;
    const int warp = tid >> 5;
    const int lane = tid & 31;
    const int mBase = blockIdx.y * 128;
    const int nBase = blockIdx.x * 128;

    #define LOAD_STAGE(sidx, kOff) do {                                           \
        uint32_t sb_ = sbase + (sidx) * STAGE_B;                                  \
        _Pragma("unroll")                                                         \
        for (int j_ = 0; j_ < 2; ++j_) {                                          \
            int c_   = tid + j_ * 256;                                            \
            int row_ = c_ >> 2;                                                   \
            int col_ = c_ & 3;                                                    \
            uint32_t dofs_ = (uint32_t)row_ * 80 + col_ * 16;                     \
            size_t gx_ = (size_t)(mBase + row_) * IN_F + (kOff) + col_ * 16;      \
            size_t gw_ = (size_t)(nBase + row_) * IN_F + (kOff) + col_ * 16;      \
            cp16(sb_ + OFF_XH + dofs_, g_xh8 + gx_);                              \
            cp16(sb_ + OFF_XL + dofs_, g_xl8 + gx_);                              \
            cp16(sb_ + OFF_WH + dofs_, g_wh8 + gw_);                              \
            cp16(sb_ + OFF_WL + dofs_, g_wl8 + gw_);                              \
        }                                                                         \
    } while (0)

    const int warp_m = warp >> 1;          // 0..3 -> 32 rows each
    const int warp_n = warp & 1;           // 0..1 -> 64 cols each
    const uint32_t aoff = (uint32_t)(warp_m * 32 + (lane & 15)) * 80 + ((lane >> 4) * 16);
    const uint32_t boff = (uint32_t)(warp_n * 64 + (lane & 7) + ((lane >> 4) << 3)) * 80
                        + (((lane >> 3) & 1) * 16);

    int hh[2][8][4], cc[2][8][4];
    #pragma unroll
    for (int i = 0; i < 2; ++i)
        #pragma unroll
        for (int j = 0; j < 8; ++j)
            #pragma unroll
            for (int q = 0; q < 4; ++q) { hh[i][j][q] = 0; cc[i][j][q] = 0; }

    LOAD_STAGE(0, 0);    CP_COMMIT();
    LOAD_STAGE(1, 64);   CP_COMMIT();
    LOAD_STAGE(2, 128);  CP_COMMIT();

    for (int kt = 0; kt < 16; ++kt) {
        CP_WAIT2();
        __syncthreads();
        const uint32_t sb = sbase + (kt % 3) * STAGE_B;

        #pragma unroll
        for (int ks = 0; ks < 2; ++ks) {
            uint32_t ah[2][4], al[2][4], bh[8][2], bl[8][2];
            #pragma unroll
            for (int i = 0; i < 2; ++i) {
                ldsm4(ah[i][0], ah[i][1], ah[i][2], ah[i][3],
                      sb + OFF_XH + aoff + i * 1280 + ks * 32);
                ldsm4(al[i][0], al[i][1], al[i][2], al[i][3],
                      sb + OFF_XL + aoff + i * 1280 + ks * 32);
            }
            #pragma unroll
            for (int j4 = 0; j4 < 4; ++j4) {
                uint32_t r0, r1, r2, r3;
                ldsm4(r0, r1, r2, r3, sb + OFF_WH + boff + j4 * 1280 + ks * 32);
                bh[j4 * 2][0] = r0; bh[j4 * 2][1] = r1;
                bh[j4 * 2 + 1][0] = r2; bh[j4 * 2 + 1][1] = r3;
                ldsm4(r0, r1, r2, r3, sb + OFF_WL + boff + j4 * 1280 + ks * 32);
                bl[j4 * 2][0] = r0; bl[j4 * 2][1] = r1;
                bl[j4 * 2 + 1][0] = r2; bl[j4 * 2 + 1][1] = r3;
            }
            #pragma unroll
            for (int i = 0; i < 2; ++i)
                #pragma unroll
                for (int j = 0; j < 8; ++j)
                    mma_s8u8(hh[i][j], ah[i][0], ah[i][1], ah[i][2], ah[i][3],
                             bh[j][0], bh[j][1]);
            #pragma unroll
            for (int i = 0; i < 2; ++i)
                #pragma unroll
                for (int j = 0; j < 8; ++j)
                    mma_s8u8(cc[i][j], ah[i][0], ah[i][1], ah[i][2], ah[i][3],
                             bl[j][0], bl[j][1]);
            #pragma unroll
            for (int i = 0; i < 2; ++i)
                #pragma unroll
                for (int j = 0; j < 8; ++j)
                    mma_s8u8(cc[i][j], al[i][0], al[i][1], al[i][2], al[i][3],
                             bh[j][0], bh[j][1]);
        }
        __syncthreads();
        if (kt + 3 < 16) LOAD_STAGE(kt % 3, (kt + 3) * 64);
        CP_COMMIT();
    }

    // ---- epilogue: y = hh*2^-11 + cc*2^-19 ----
    const float S_HH = 4.8828125e-4f;        // 2^-11
    const float S_CC = 1.9073486328125e-6f;  // 2^-19
    const int mrow = mBase + warp_m * 32 + (lane >> 2);
    const int ncol = nBase + warp_n * 64 + (lane & 3) * 2;
    #pragma unroll
    for (int i = 0; i < 2; ++i) {
        #pragma unroll
        for (int j = 0; j < 8; ++j) {
            int m0 = mrow + i * 16;
            int n0 = ncol + j * 8;
            float v0 = fmaf((float)hh[i][j][0], S_HH, (float)cc[i][j][0] * S_CC);
            float v1 = fmaf((float)hh[i][j][1], S_HH, (float)cc[i][j][1] * S_CC);
            float v2 = fmaf((float)hh[i][j][2], S_HH, (float)cc[i][j][2] * S_CC);
            float v3 = fmaf((float)hh[i][j][3], S_HH, (float)cc[i][j][3] * S_CC);
            *(float2*)&y[(size_t)m0 * OUT_F + n0]       = make_float2(v0, v1);
            *(float2*)&y[(size_t)(m0 + 8) * OUT_F + n0] = make_float2(v2, v3);
        }
    }
    #undef LOAD_STAGE
}

// ---------------- K2: per-batch-row top-2 + xx + gather lists ----------------
// one warp per row; full unroll (16 float4 loads in flight) + dual compare chains
__global__ __launch_bounds__(256) void topk_kernel(const float* __restrict__ y) {
    int b    = (blockIdx.x * blockDim.x + threadIdx.x) >> 5;
    int lane = threadIdx.x & 31;
    if (b >= BATCH) return;
    const float4* row4 = (const float4*)(y + (size_t)b * OUT_F);

    float v1a = -INFINITY, v2a = -INFINITY; int c1a = 0x7fffffff, c2a = 0x7fffffff;
    float v1b = -INFINITY, v2b = -INFINITY; int c1b = 0x7fffffff, c2b = 0x7fffffff;
    #pragma unroll
    for (int it = 0; it < OUT_F / 128; ++it) {       // 16 iterations, fully unrolled
        int c4 = lane + it * 32;
        float4 v = row4[c4];
        int base = c4 * 4;
        top2_add(v1a, c1a, v2a, c2a, v.x, base);
        top2_add(v1a, c1a, v2a, c2a, v.y, base + 1);
        top2_add(v1b, c1b, v2b, c2b, v.z, base + 2);
        top2_add(v1b, c1b, v2b, c2b, v.w, base + 3);
    }
    merge2(v1a, c1a, v2a, c2a, v1b, c1b, v2b, c2b);  // chain B indices always > chain A? no: tie-safe merge
    #pragma unroll
    for (int off = 16; off > 0; off >>= 1) {
        float w1 = __shfl_down_sync(0xffffffffu, v1a, off);
        int   j1 = __shfl_down_sync(0xffffffffu, c1a, off);
        float w2 = __shfl_down_sync(0xffffffffu, v2a, off);
        int   j2 = __shfl_down_sync(0xffffffffu, c2a, off);
        merge2(v1a, c1a, v2a, c2a, w1, j1, w2, j2);
    }
    if (lane == 0) {
        int s1 = atomicAdd(&g_cnt1[c1a], 1);
        g_list1[c1a * BATCH + s1] = b;
        int s2 = atomicAdd(&g_cnt2[c2a], 1);
        g_list2[c2a * BATCH + s2] = b;
        atomicAdd(&g_xx[c1a], v1a);
        atomicAdd(&g_xx[c2a], -0.4f * v2a);
    }
}

// ---------------- K3: fused ds = yl@x - xx*W  and  nc = max|ds| ----------------
__global__ __launch_bounds__(256) void ds_kernel(const float* __restrict__ x,
                                                 const float* __restrict__ W) {
    __shared__ float red[8];
    const int o = blockIdx.x;
    const int t = threadIdx.x;
    float4 wv = ((const float4*)W)[o * 256 + t];
    float s = -g_xx[o];
    float4 acc = make_float4(s * wv.x, s * wv.y, s * wv.z, s * wv.w);

    const int n1 = g_cnt1[o];
    const int* l1 = g_list1 + (size_t)o * BATCH;
    int j = 0;
    for (; j + 1 < n1; j += 2) {
        int b0 = l1[j], b1 = l1[j + 1];
        float4 x0 = ((const float4*)x)[b0 * 256 + t];
        float4 x1 = ((const float4*)x)[b1 * 256 + t];
        acc.x += x0.x + x1.x; acc.y += x0.y + x1.y;
        acc.z += x0.z + x1.z; acc.w += x0.w + x1.w;
    }
    if (j < n1) {
        float4 x0 = ((const float4*)x)[l1[j] * 256 + t];
        acc.x += x0.x; acc.y += x0.y; acc.z += x0.z; acc.w += x0.w;
    }
    const int n2 = g_cnt2[o];
    const int* l2 = g_list2 + (size_t)o * BATCH;
    j = 0;
    for (; j + 1 < n2; j += 2) {
        int b0 = l2[j], b1 = l2[j + 1];
        float4 x0 = ((const float4*)x)[b0 * 256 + t];
        float4 x1 = ((const float4*)x)[b1 * 256 + t];
        acc.x -= 0.4f * (x0.x + x1.x); acc.y -= 0.4f * (x0.y + x1.y);
        acc.z -= 0.4f * (x0.z + x1.z); acc.w -= 0.4f * (x0.w + x1.w);
    }
    if (j < n2) {
        float4 x0 = ((const float4*)x)[l2[j] * 256 + t];
        acc.x -= 0.4f * x0.x; acc.y -= 0.4f * x0.y;
        acc.z -= 0.4f * x0.z; acc.w -= 0.4f * x0.w;
    }
    ((float4*)g_ds)[o * 256 + t] = acc;

    float m = fmaxf(fmaxf(fabsf(acc.x), fabsf(acc.y)), fmaxf(fabsf(acc.z), fabsf(acc.w)));
    #pragma unroll
    for (int off = 16; off > 0; off >>= 1)
        m = fmaxf(m, __shfl_down_sync(0xffffffffu, m, off));
    if ((t & 31) == 0) red[t >> 5] = m;
    __syncthreads();
    if (t < 8) {
        float v = red[t];
        #pragma unroll
        for (int off = 4; off > 0; off >>= 1)
            v = fmaxf(v, __shfl_down_sync(0xffu, v, off));
        if (t == 0) atomicMax(&g_ncbits, __float_as_uint(v));
    }
}

// ---------------- K4: new_W = W + 0.02 * ds / nc ----------------
__global__ void update_kernel(const float* __restrict__ W, float* __restrict__ outW) {
    float nc = fmaxf(__uint_as_float(g_ncbits), 1e-30f);
    float s  = 0.02f / nc;
    int t = blockIdx.x * blockDim.x + threadIdx.x;
    float4 w = ((const float4*)W)[t];
    float4 d = ((const float4*)g_ds)[t];
    ((float4*)outW)[t] = make_float4(fmaf(s, d.x, w.x), fmaf(s, d.y, w.y),
                                     fmaf(s, d.z, w.z), fmaf(s, d.w, w.w));
}

// ---------------- launch ----------------
extern "C" void kernel_launch(void* const* d_in, const int* in_sizes, int n_in,
                              void* d_out, int out_size) {
    const float* x = (const float*)d_in[0];   // [8192, 1024] f32
    const float* w = (const float*)d_in[1];   // [2048, 1024] f32
    float* y    = (float*)d_out;                              // [8192, 2048]
    float* outW = (float*)d_out + (size_t)BATCH * OUT_F;      // [2048, 1024]

    cudaFuncSetAttribute(gemm_kernel, cudaFuncAttributeMaxDynamicSharedMemorySize, GEMM_SMEM);

    const int NTOT4 = (BATCH * IN_F + OUT_F * IN_F) / 4;
    convert_kernel<<<(NTOT4 + 255) / 256, 256>>>(x, w);
    gemm_kernel<<<dim3(OUT_F / 128, BATCH / 128), 256, GEMM_SMEM>>>(y);
    topk_kernel<<<BATCH / 8, 256>>>(y);
    ds_kernel<<<OUT_F, 256>>>(x, w);
    update_kernel<<<(OUT_F * IN_F / 4) / 256, 256>>>(w, outW);
}

// round 10
// speedup vs baseline: 1.0759x; 1.0092x over previous
#include <cuda_runtime.h>
#include <math.h>
#include <stdint.h>

#define BATCH 8192
#define IN_F  1024
#define OUT_F 2048

// ---------------- device scratch (static; no allocations) ----------------
__device__ signed char   g_xh8[BATCH * IN_F];
__device__ signed char   g_xl8[BATCH * IN_F];
__device__ unsigned char g_wh8[OUT_F * IN_F];
__device__ unsigned char g_wl8[OUT_F * IN_F];
__device__ float        g_xx[OUT_F];
__device__ int          g_cnt1[OUT_F];
__device__ int          g_cnt2[OUT_F];
__device__ int          g_list1[OUT_F * BATCH];
__device__ int          g_list2[OUT_F * BATCH];
__device__ float        g_ds[OUT_F * IN_F];
__device__ unsigned int g_ncbits;

// ---------------- helpers ----------------
__device__ __forceinline__ uint32_t smem_u32(const void* p) {
    uint32_t a;
    asm("{ .reg .u64 t; cvta.to.shared.u64 t, %1; cvt.u32.u64 %0, t; }" : "=r"(a) : "l"(p));
    return a;
}
__device__ __forceinline__ void cp16(uint32_t dst, const void* src) {
    asm volatile("cp.async.cg.shared.global [%0], [%1], 16;\n" :: "r"(dst), "l"(src));
}
#define CP_COMMIT() asm volatile("cp.async.commit_group;\n" ::: "memory")
#define CP_WAIT2()  asm volatile("cp.async.wait_group 2;\n" ::: "memory")

__device__ __forceinline__ void ldsm4(uint32_t& r0, uint32_t& r1, uint32_t& r2, uint32_t& r3,
                                      uint32_t addr) {
    asm volatile("ldmatrix.sync.aligned.m8n8.x4.shared.b16 {%0,%1,%2,%3}, [%4];\n"
                 : "=r"(r0), "=r"(r1), "=r"(r2), "=r"(r3) : "r"(addr));
}
__device__ __forceinline__ void mma_s8u8(int* c, uint32_t a0, uint32_t a1, uint32_t a2,
                                         uint32_t a3, uint32_t b0, uint32_t b1) {
    asm volatile("mma.sync.aligned.m16n8k32.row.col.s32.s8.u8.s32 "
                 "{%0,%1,%2,%3}, {%4,%5,%6,%7}, {%8,%9}, {%0,%1,%2,%3};\n"
                 : "+r"(c[0]), "+r"(c[1]), "+r"(c[2]), "+r"(c[3])
                 : "r"(a0), "r"(a1), "r"(a2), "r"(a3), "r"(b0), "r"(b1));
}
// store float2 with L2::evict_last policy (keep y resident for topk re-read)
__device__ __forceinline__ void st_f2_evl(float* p, float a, float b, uint64_t pol) {
    asm volatile("st.global.L2::cache_hint.v2.f32 [%0], {%1, %2}, %3;"
                 :: "l"(p), "f"(a), "f"(b), "l"(pol) : "memory");
}

// merge a sorted top-2 pair (w1,j1,w2,j2) into (v1,c1,v2,c2); ties -> lower index
__device__ __forceinline__ void merge2(float& v1, int& c1, float& v2, int& c2,
                                       float w1, int j1, float w2, int j2) {
    if (w1 > v1 || (w1 == v1 && j1 < c1)) {
        float t = v1; int tc = c1;
        if (w2 > t || (w2 == t && j2 < tc)) { t = w2; tc = j2; }
        v2 = t; c2 = tc; v1 = w1; c1 = j1;
    } else {
        if (w1 > v2 || (w1 == v2 && j1 < c2)) { v2 = w1; c2 = j1; }
    }
}

// ---------------- K0: quantize fp32 -> int16 fixed point + zero accumulators ----------------
__global__ __launch_bounds__(256) void convert_kernel(const float* __restrict__ x,
                                                      const float* __restrict__ w) {
    const int NX4 = BATCH * IN_F / 4;
    const int NW4 = OUT_F * IN_F / 4;
    int t = blockIdx.x * blockDim.x + threadIdx.x;
    if (t < OUT_F) { g_xx[t] = 0.0f; g_cnt1[t] = 0; g_cnt2[t] = 0; }
    if (t == 0)    g_ncbits = 0u;
    if (t < NX4) {
        float4 v = ((const float4*)x)[t];
        uchar4 h, l;
        #pragma unroll
        for (int q = 0; q < 4; ++q) {
            float f = (&v.x)[q];
            int xq = __float2int_rn(f * 4096.0f);
            xq = max(min(xq, 32512), -32512);
            int hx = (xq + 128) >> 8;
            int lx = xq - (hx << 8);
            (&h.x)[q] = (unsigned char)(signed char)hx;
            (&l.x)[q] = (unsigned char)(signed char)lx;
        }
        ((uchar4*)g_xh8)[t] = h;
        ((uchar4*)g_xl8)[t] = l;
    } else if (t < NX4 + NW4) {
        int u = t - NX4;
        float4 v = ((const float4*)w)[u];
        uchar4 h, l;
        #pragma unroll
        for (int q = 0; q < 4; ++q) {
            float f = (&v.x)[q];
            int wq = __float2int_rn(f * 32768.0f);
            wq = max(min(wq, 32767), 0);
            (&h.x)[q] = (unsigned char)(wq >> 8);
            (&l.x)[q] = (unsigned char)(wq & 255);
        }
        ((uchar4*)g_wh8)[u] = h;
        ((uchar4*)g_wl8)[u] = l;
    }
}

// ---------------- K1: int8x3 GEMM via mma.sync  y = x @ W^T ----------------
#define TILE_B  10240          // 128 rows * 80 B
#define OFF_XH  0
#define OFF_XL  10240
#define OFF_WH  20480
#define OFF_WL  30720
#define STAGE_B 40960
#define GEMM_SMEM (3 * STAGE_B)

__global__ __launch_bounds__(256, 1) void gemm_kernel(float* __restrict__ y) {
    extern __shared__ char smem[];
    const uint32_t sbase = smem_u32(smem);
    const int tid  = threadIdx.x;
    const int warp = tid >> 5;
    const int lane = tid & 31;
    const int mBase = blockIdx.y * 128;
    const int nBase = blockIdx.x * 128;

    #define LOAD_STAGE(sidx, kOff) do {                                           \
        uint32_t sb_ = sbase + (sidx) * STAGE_B;                                  \
        _Pragma("unroll")                                                         \
        for (int j_ = 0; j_ < 2; ++j_) {                                          \
            int c_   = tid + j_ * 256;                                            \
            int row_ = c_ >> 2;                                                   \
            int col_ = c_ & 3;                                                    \
            uint32_t dofs_ = (uint32_t)row_ * 80 + col_ * 16;                     \
            size_t gx_ = (size_t)(mBase + row_) * IN_F + (kOff) + col_ * 16;      \
            size_t gw_ = (size_t)(nBase + row_) * IN_F + (kOff) + col_ * 16;      \
            cp16(sb_ + OFF_XH + dofs_, g_xh8 + gx_);                              \
            cp16(sb_ + OFF_XL + dofs_, g_xl8 + gx_);                              \
            cp16(sb_ + OFF_WH + dofs_, g_wh8 + gw_);                              \
            cp16(sb_ + OFF_WL + dofs_, g_wl8 + gw_);                              \
        }                                                                         \
    } while (0)

    const int warp_m = warp >> 1;          // 0..3 -> 32 rows each
    const int warp_n = warp & 1;           // 0..1 -> 64 cols each
    const uint32_t aoff = (uint32_t)(warp_m * 32 + (lane & 15)) * 80 + ((lane >> 4) * 16);
    const uint32_t boff = (uint32_t)(warp_n * 64 + (lane & 7) + ((lane >> 4) << 3)) * 80
                        + (((lane >> 3) & 1) * 16);

    int hh[2][8][4], cc[2][8][4];
    #pragma unroll
    for (int i = 0; i < 2; ++i)
        #pragma unroll
        for (int j = 0; j < 8; ++j)
            #pragma unroll
            for (int q = 0; q < 4; ++q) { hh[i][j][q] = 0; cc[i][j][q] = 0; }

    LOAD_STAGE(0, 0);    CP_COMMIT();
    LOAD_STAGE(1, 64);   CP_COMMIT();
    LOAD_STAGE(2, 128);  CP_COMMIT();

    for (int kt = 0; kt < 16; ++kt) {
        CP_WAIT2();
        __syncthreads();
        const uint32_t sb = sbase + (kt % 3) * STAGE_B;

        #pragma unroll
        for (int ks = 0; ks < 2; ++ks) {
            uint32_t ah[2][4], al[2][4], bh[8][2], bl[8][2];
            #pragma unroll
            for (int i = 0; i < 2; ++i) {
                ldsm4(ah[i][0], ah[i][1], ah[i][2], ah[i][3],
                      sb + OFF_XH + aoff + i * 1280 + ks * 32);
                ldsm4(al[i][0], al[i][1], al[i][2], al[i][3],
                      sb + OFF_XL + aoff + i * 1280 + ks * 32);
            }
            #pragma unroll
            for (int j4 = 0; j4 < 4; ++j4) {
                uint32_t r0, r1, r2, r3;
                ldsm4(r0, r1, r2, r3, sb + OFF_WH + boff + j4 * 1280 + ks * 32);
                bh[j4 * 2][0] = r0; bh[j4 * 2][1] = r1;
                bh[j4 * 2 + 1][0] = r2; bh[j4 * 2 + 1][1] = r3;
                ldsm4(r0, r1, r2, r3, sb + OFF_WL + boff + j4 * 1280 + ks * 32);
                bl[j4 * 2][0] = r0; bl[j4 * 2][1] = r1;
                bl[j4 * 2 + 1][0] = r2; bl[j4 * 2 + 1][1] = r3;
            }
            #pragma unroll
            for (int i = 0; i < 2; ++i)
                #pragma unroll
                for (int j = 0; j < 8; ++j)
                    mma_s8u8(hh[i][j], ah[i][0], ah[i][1], ah[i][2], ah[i][3],
                             bh[j][0], bh[j][1]);
            #pragma unroll
            for (int i = 0; i < 2; ++i)
                #pragma unroll
                for (int j = 0; j < 8; ++j)
                    mma_s8u8(cc[i][j], ah[i][0], ah[i][1], ah[i][2], ah[i][3],
                             bl[j][0], bl[j][1]);
            #pragma unroll
            for (int i = 0; i < 2; ++i)
                #pragma unroll
                for (int j = 0; j < 8; ++j)
                    mma_s8u8(cc[i][j], al[i][0], al[i][1], al[i][2], al[i][3],
                             bh[j][0], bh[j][1]);
        }
        __syncthreads();
        if (kt + 3 < 16) LOAD_STAGE(kt % 3, (kt + 3) * 64);
        CP_COMMIT();
    }

    // ---- epilogue: y = hh*2^-11 + cc*2^-19, stored with L2 evict_last ----
    const float S_HH = 4.8828125e-4f;        // 2^-11
    const float S_CC = 1.9073486328125e-6f;  // 2^-19
    uint64_t pol;
    asm("createpolicy.fractional.L2::evict_last.b64 %0, 1.0;" : "=l"(pol));
    const int mrow = mBase + warp_m * 32 + (lane >> 2);
    const int ncol = nBase + warp_n * 64 + (lane & 3) * 2;
    #pragma unroll
    for (int i = 0; i < 2; ++i) {
        #pragma unroll
        for (int j = 0; j < 8; ++j) {
            int m0 = mrow + i * 16;
            int n0 = ncol + j * 8;
            float v0 = fmaf((float)hh[i][j][0], S_HH, (float)cc[i][j][0] * S_CC);
            float v1 = fmaf((float)hh[i][j][1], S_HH, (float)cc[i][j][1] * S_CC);
            float v2 = fmaf((float)hh[i][j][2], S_HH, (float)cc[i][j][2] * S_CC);
            float v3 = fmaf((float)hh[i][j][3], S_HH, (float)cc[i][j][3] * S_CC);
            st_f2_evl(&y[(size_t)m0 * OUT_F + n0],       v0, v1, pol);
            st_f2_evl(&y[(size_t)(m0 + 8) * OUT_F + n0], v2, v3, pol);
        }
    }
    #undef LOAD_STAGE
}

// ---------------- K2: per-batch-row top-2 + xx + gather lists (round-6 proven) ----------------
__global__ void topk_kernel(const float* __restrict__ y) {
    int b    = (blockIdx.x * blockDim.x + threadIdx.x) >> 5;
    int lane = threadIdx.x & 31;
    if (b >= BATCH) return;
    const float4* row4 = (const float4*)(y + (size_t)b * OUT_F);

    float v1 = -INFINITY, v2 = -INFINITY;
    int   i1 = 0x7fffffff, i2 = 0x7fffffff;
    #pragma unroll 4
    for (int it = 0; it < OUT_F / 128; ++it) {
        int c4 = lane + it * 32;
        float4 v = row4[c4];
        int base = c4 * 4;
        #pragma unroll
        for (int q = 0; q < 4; ++q) {
            float f = (&v.x)[q];
            int idx = base + q;
            if (f > v1)      { v2 = v1; i2 = i1; v1 = f; i1 = idx; }
            else if (f > v2) { v2 = f;  i2 = idx; }
        }
    }
    #pragma unroll
    for (int off = 16; off > 0; off >>= 1) {
        float w1 = __shfl_down_sync(0xffffffffu, v1, off);
        int   j1 = __shfl_down_sync(0xffffffffu, i1, off);
        float w2 = __shfl_down_sync(0xffffffffu, v2, off);
        int   j2 = __shfl_down_sync(0xffffffffu, i2, off);
        merge2(v1, i1, v2, i2, w1, j1, w2, j2);
    }
    if (lane == 0) {
        int s1 = atomicAdd(&g_cnt1[i1], 1);
        g_list1[i1 * BATCH + s1] = b;
        int s2 = atomicAdd(&g_cnt2[i2], 1);
        g_list2[i2 * BATCH + s2] = b;
        atomicAdd(&g_xx[i1], v1);
        atomicAdd(&g_xx[i2], -0.4f * v2);
    }
}

// ---------------- K3: fused ds = yl@x - xx*W  and  nc = max|ds| ----------------
__global__ __launch_bounds__(256) void ds_kernel(const float* __restrict__ x,
                                                 const float* __restrict__ W) {
    __shared__ float red[8];
    const int o = blockIdx.x;
    const int t = threadIdx.x;
    float4 wv = ((const float4*)W)[o * 256 + t];
    float s = -g_xx[o];
    float4 acc = make_float4(s * wv.x, s * wv.y, s * wv.z, s * wv.w);

    const int n1 = g_cnt1[o];
    const int* l1 = g_list1 + (size_t)o * BATCH;
    int j = 0;
    for (; j + 1 < n1; j += 2) {
        int b0 = l1[j], b1 = l1[j + 1];
        float4 x0 = ((const float4*)x)[b0 * 256 + t];
        float4 x1 = ((const float4*)x)[b1 * 256 + t];
        acc.x += x0.x + x1.x; acc.y += x0.y + x1.y;
        acc.z += x0.z + x1.z; acc.w += x0.w + x1.w;
    }
    if (j < n1) {
        float4 x0 = ((const float4*)x)[l1[j] * 256 + t];
        acc.x += x0.x; acc.y += x0.y; acc.z += x0.z; acc.w += x0.w;
    }
    const int n2 = g_cnt2[o];
    const int* l2 = g_list2 + (size_t)o * BATCH;
    j = 0;
    for (; j + 1 < n2; j += 2) {
        int b0 = l2[j], b1 = l2[j + 1];
        float4 x0 = ((const float4*)x)[b0 * 256 + t];
        float4 x1 = ((const float4*)x)[b1 * 256 + t];
        acc.x -= 0.4f * (x0.x + x1.x); acc.y -= 0.4f * (x0.y + x1.y);
        acc.z -= 0.4f * (x0.z + x1.z); acc.w -= 0.4f * (x0.w + x1.w);
    }
    if (j < n2) {
        float4 x0 = ((const float4*)x)[l2[j] * 256 + t];
        acc.x -= 0.4f * x0.x; acc.y -= 0.4f * x0.y;
        acc.z -= 0.4f * x0.z; acc.w -= 0.4f * x0.w;
    }
    ((float4*)g_ds)[o * 256 + t] = acc;

    float m = fmaxf(fmaxf(fabsf(acc.x), fabsf(acc.y)), fmaxf(fabsf(acc.z), fabsf(acc.w)));
    #pragma unroll
    for (int off = 16; off > 0; off >>= 1)
        m = fmaxf(m, __shfl_down_sync(0xffffffffu, m, off));
    if ((t & 31) == 0) red[t >> 5] = m;
    __syncthreads();
    if (t < 8) {
        float v = red[t];
        #pragma unroll
        for (int off = 4; off > 0; off >>= 1)
            v = fmaxf(v, __shfl_down_sync(0xffu, v, off));
        if (t == 0) atomicMax(&g_ncbits, __float_as_uint(v));
    }
}

// ---------------- K4: new_W = W + 0.02 * ds / nc ----------------
__global__ void update_kernel(const float* __restrict__ W, float* __restrict__ outW) {
    float nc = fmaxf(__uint_as_float(g_ncbits), 1e-30f);
    float s  = 0.02f / nc;
    int t = blockIdx.x * blockDim.x + threadIdx.x;
    float4 w = ((const float4*)W)[t];
    float4 d = ((const float4*)g_ds)[t];
    ((float4*)outW)[t] = make_float4(fmaf(s, d.x, w.x), fmaf(s, d.y, w.y),
                                     fmaf(s, d.z, w.z), fmaf(s, d.w, w.w));
}

// ---------------- launch ----------------
extern "C" void kernel_launch(void* const* d_in, const int* in_sizes, int n_in,
                              void* d_out, int out_size) {
    const float* x = (const float*)d_in[0];   // [8192, 1024] f32
    const float* w = (const float*)d_in[1];   // [2048, 1024] f32
    float* y    = (float*)d_out;                              // [8192, 2048]
    float* outW = (float*)d_out + (size_t)BATCH * OUT_F;      // [2048, 1024]

    cudaFuncSetAttribute(gemm_kernel, cudaFuncAttributeMaxDynamicSharedMemorySize, GEMM_SMEM);

    const int NTOT4 = (BATCH * IN_F + OUT_F * IN_F) / 4;
    convert_kernel<<<(NTOT4 + 255) / 256, 256>>>(x, w);
    gemm_kernel<<<dim3(OUT_F / 128, BATCH / 128), 256, GEMM_SMEM>>>(y);
    topk_kernel<<<BATCH / 4, 128>>>(y);
    ds_kernel<<<OUT_F, 256>>>(x, w);
    update_kernel<<<(OUT_F * IN_F / 4) / 256, 256>>>(w, outW);
}